// round 3
// baseline (speedup 1.0000x reference)
#include <cuda_runtime.h>
#include <math.h>

#define NV   65536
#define CH   128
#define NSEGS 1024
#define KT   27
#define NC   (NV*CH)

typedef unsigned long long u64;
typedef unsigned int u32;

__device__ __forceinline__ u64 pk2(float x) {
    u64 r; asm("mov.b64 %0, {%1, %1};" : "=l"(r) : "f"(x)); return r;
}
__device__ __forceinline__ void fma2(u64 &d, u64 a, u64 b) {
    asm("fma.rn.f32x2 %0, %1, %2, %0;" : "+l"(d) : "l"(a), "l"(b));
}
__device__ __forceinline__ float2 upk(u64 v) {
    float2 f; asm("mov.b64 {%0, %1}, %2;" : "=f"(f.x), "=f"(f.y) : "l"(v)); return f;
}
__device__ __forceinline__ u32 enc_max(float f) {
    u32 u = __float_as_uint(f);
    return (u & 0x80000000u) ? ~u : (u | 0x80000000u);
}
__device__ __forceinline__ float dec_max(u32 k) {
    u32 u = (k & 0x80000000u) ? (k & 0x7FFFFFFFu) : ~k;
    return __uint_as_float(u);
}
__device__ __forceinline__ float lrelu(float v) { return v >= 0.f ? v : 0.01f * v; }

// ---------------- scratch ----------------------------------------------------
__device__ float g_pw[NC];
__device__ float g_t[NC];
__device__ float g_pf[NC];
__device__ float g_agg[NC];
__device__ float g_fused[NC];
__device__ float g_ybuf[NC];
__device__ float g_dbuf[NC];
__device__ float g_adp[NV*3];
__device__ float g_segmean[NSEGS*CH];
__device__ float g_segexp[NSEGS*CH];
__device__ float g_seg2[3*NSEGS*CH];
__device__ float g_sum[CH];
__device__ float g_sumsq[CH];
__device__ float g_scale[CH];
__device__ float g_bias[CH];
__device__ int   g_cnt[NSEGS];
__device__ int   g_tail[NSEGS];
__device__ int   g_off[NSEGS+1];
__device__ int   g_order[NV];
__device__ u32   g_gmaxu[1];

// ---------------- dense GEMM: C[N,128] (+)= A[N,128] @ W[128,128] ------------
// PRO: 0 plain A, 1 A -> lrelu(A*scp+sbp). EPI: 0 none, 1 colstats, 2 global max
template<int PRO, int EPI>
__global__ __launch_bounds__(256, 2) void gemm128(const float* __restrict__ A,
        const float* __restrict__ W, float* __restrict__ Cc, int acc,
        const float* __restrict__ scp, const float* __restrict__ sbp,
        float* __restrict__ sumP, float* __restrict__ sumqP, u32* __restrict__ gmaxP)
{
    __shared__ float Asd[16][256];   // A duplicated pairs: Asd[k][2r]=Asd[k][2r+1]=A[r][k]
    __shared__ float Ws[16][128];
    __shared__ float red0[128], red1[128];
    const int tid = threadIdx.x;
    const int brow = blockIdx.x * 128;
    const int tx = tid & 15, ty = tid >> 4;
    const int ar = tid >> 1, ac = (tid & 1) * 8;
    const int wr = tid >> 4, wc = (tid & 15) * 8;

    if (PRO) {
        if (tid < 128) { red0[tid] = scp[tid]; red1[tid] = sbp[tid]; }
        __syncthreads();
    }
    float scl[8], sbl[8];
    if (PRO) {
#pragma unroll
        for (int j = 0; j < 8; j++) { scl[j] = 0.f; sbl[j] = 0.f; }
    }

    u64 acc2[8][4];
#pragma unroll
    for (int i = 0; i < 8; i++)
#pragma unroll
        for (int j = 0; j < 4; j++) acc2[i][j] = 0ull;

    const float* Arow = A + (size_t)(brow + ar) * CH;
#pragma unroll 1
    for (int k0 = 0; k0 < CH; k0 += 16) {
        float4 a0 = *(const float4*)(Arow + k0 + ac);
        float4 a1 = *(const float4*)(Arow + k0 + ac + 4);
        float av8[8] = {a0.x, a0.y, a0.z, a0.w, a1.x, a1.y, a1.z, a1.w};
        if (PRO) {
#pragma unroll
            for (int j = 0; j < 8; j++)
                av8[j] = lrelu(av8[j] * red0[k0 + ac + j] + red1[k0 + ac + j]);
        }
#pragma unroll
        for (int j = 0; j < 8; j++)
            *(u64*)&Asd[ac + j][2 * ar] = pk2(av8[j]);
        const float* Wp = W + (size_t)(k0 + wr) * CH + wc;
        *(float4*)&Ws[wr][wc]     = *(const float4*)Wp;
        *(float4*)&Ws[wr][wc + 4] = *(const float4*)(Wp + 4);
        __syncthreads();
#pragma unroll
        for (int kk = 0; kk < 16; kk++) {
            ulonglong2 A01 = *(const ulonglong2*)&Asd[kk][ty * 16 + 0];
            ulonglong2 A23 = *(const ulonglong2*)&Asd[kk][ty * 16 + 4];
            ulonglong2 A45 = *(const ulonglong2*)&Asd[kk][ty * 16 + 8];
            ulonglong2 A67 = *(const ulonglong2*)&Asd[kk][ty * 16 + 12];
            double2 wq0 = *(const double2*)&Ws[kk][tx * 8];
            double2 wq1 = *(const double2*)&Ws[kk][tx * 8 + 4];
            u64 w0 = __double_as_longlong(wq0.x);
            u64 w1 = __double_as_longlong(wq0.y);
            u64 w2 = __double_as_longlong(wq1.x);
            u64 w3 = __double_as_longlong(wq1.y);
            u64 av[8] = {A01.x, A01.y, A23.x, A23.y, A45.x, A45.y, A67.x, A67.y};
#pragma unroll
            for (int i = 0; i < 8; i++) {
                fma2(acc2[i][0], av[i], w0);
                fma2(acc2[i][1], av[i], w1);
                fma2(acc2[i][2], av[i], w2);
                fma2(acc2[i][3], av[i], w3);
            }
        }
        __syncthreads();
    }

    float colS[8], colQ[8];
#pragma unroll
    for (int j = 0; j < 8; j++) { colS[j] = 0.f; colQ[j] = 0.f; }
    float bmax = -3.4e38f;

#pragma unroll
    for (int i = 0; i < 8; i++) {
        float* Cp = Cc + (size_t)(brow + ty * 8 + i) * CH + tx * 8;
        float2 p0 = upk(acc2[i][0]), p1 = upk(acc2[i][1]);
        float2 p2 = upk(acc2[i][2]), p3 = upk(acc2[i][3]);
        float c[8] = {p0.x, p0.y, p1.x, p1.y, p2.x, p2.y, p3.x, p3.y};
        if (acc) {
            float4 o0 = *(const float4*)Cp, o1 = *(const float4*)(Cp + 4);
            c[0] += o0.x; c[1] += o0.y; c[2] += o0.z; c[3] += o0.w;
            c[4] += o1.x; c[5] += o1.y; c[6] += o1.z; c[7] += o1.w;
        }
        if (EPI == 1) {
#pragma unroll
            for (int j = 0; j < 8; j++) { colS[j] += c[j]; colQ[j] += c[j] * c[j]; }
        }
        if (EPI == 2) {
#pragma unroll
            for (int j = 0; j < 8; j++) bmax = fmaxf(bmax, c[j]);
        }
        *(float4*)Cp       = make_float4(c[0], c[1], c[2], c[3]);
        *(float4*)(Cp + 4) = make_float4(c[4], c[5], c[6], c[7]);
    }

    if (EPI == 1) {
        __syncthreads();
        if (tid < 128) { red0[tid] = 0.f; red1[tid] = 0.f; }
        __syncthreads();
#pragma unroll
        for (int j = 0; j < 8; j++) {
            atomicAdd(&red0[tx * 8 + j], colS[j]);
            atomicAdd(&red1[tx * 8 + j], colQ[j]);
        }
        __syncthreads();
        if (tid < 128) {
            atomicAdd(&sumP[tid],  red0[tid]);
            atomicAdd(&sumqP[tid], red1[tid]);
        }
    }
    if (EPI == 2) {
#pragma unroll
        for (int o = 16; o; o >>= 1)
            bmax = fmaxf(bmax, __shfl_xor_sync(0xffffffffu, bmax, o));
        if ((tid & 31) == 0) atomicMax(gmaxP, enc_max(bmax));
    }
}

// -------- sparse conv (27 taps), optional bn+lrelu prologue, colstats epi ----
template<int PRO>
__global__ __launch_bounds__(256, 2) void sconv128(const float* __restrict__ X,
        const int* __restrict__ nbr, const float* __restrict__ W,
        float* __restrict__ Out, const float* __restrict__ scp,
        const float* __restrict__ sbp, float* __restrict__ sumP,
        float* __restrict__ sumqP)
{
    __shared__ float Asd[16][256];
    __shared__ float Ws[16][128];
    __shared__ int nid[128];
    __shared__ float sct[128], sbt[128];
    const int tid = threadIdx.x;
    const int brow = blockIdx.x * 128;
    const int tx = tid & 15, ty = tid >> 4;
    const int ar = tid >> 1, ac = (tid & 1) * 8;
    const int wr = tid >> 4, wc = (tid & 15) * 8;

    if (PRO) {
        if (tid < 128) { sct[tid] = scp[tid]; sbt[tid] = sbp[tid]; }
    }
    __syncthreads();

    u64 acc2[8][4];
#pragma unroll
    for (int i = 0; i < 8; i++)
#pragma unroll
        for (int j = 0; j < 4; j++) acc2[i][j] = 0ull;

#pragma unroll 1
    for (int k = 0; k < KT; k++) {
        if (tid < 128) nid[tid] = nbr[(size_t)(brow + tid) * KT + k];
        __syncthreads();
        const int nrow = nid[ar];
        const bool valid = (nrow < NV);
        const float* Xrow = X + (size_t)(valid ? nrow : 0) * CH;
        const float* Wk = W + (size_t)k * CH * CH;
#pragma unroll 1
        for (int k0 = 0; k0 < CH; k0 += 16) {
            float av8[8];
            if (valid) {
                float4 a0 = *(const float4*)(Xrow + k0 + ac);
                float4 a1 = *(const float4*)(Xrow + k0 + ac + 4);
                av8[0] = a0.x; av8[1] = a0.y; av8[2] = a0.z; av8[3] = a0.w;
                av8[4] = a1.x; av8[5] = a1.y; av8[6] = a1.z; av8[7] = a1.w;
                if (PRO) {
#pragma unroll
                    for (int j = 0; j < 8; j++)
                        av8[j] = lrelu(av8[j] * sct[k0 + ac + j] + sbt[k0 + ac + j]);
                }
            } else {
#pragma unroll
                for (int j = 0; j < 8; j++) av8[j] = 0.f;
            }
#pragma unroll
            for (int j = 0; j < 8; j++)
                *(u64*)&Asd[ac + j][2 * ar] = pk2(av8[j]);
            const float* Wp = Wk + (size_t)(k0 + wr) * CH + wc;
            *(float4*)&Ws[wr][wc]     = *(const float4*)Wp;
            *(float4*)&Ws[wr][wc + 4] = *(const float4*)(Wp + 4);
            __syncthreads();
#pragma unroll
            for (int kk = 0; kk < 16; kk++) {
                ulonglong2 A01 = *(const ulonglong2*)&Asd[kk][ty * 16 + 0];
                ulonglong2 A23 = *(const ulonglong2*)&Asd[kk][ty * 16 + 4];
                ulonglong2 A45 = *(const ulonglong2*)&Asd[kk][ty * 16 + 8];
                ulonglong2 A67 = *(const ulonglong2*)&Asd[kk][ty * 16 + 12];
                double2 wq0 = *(const double2*)&Ws[kk][tx * 8];
                double2 wq1 = *(const double2*)&Ws[kk][tx * 8 + 4];
                u64 w0 = __double_as_longlong(wq0.x);
                u64 w1 = __double_as_longlong(wq0.y);
                u64 w2 = __double_as_longlong(wq1.x);
                u64 w3 = __double_as_longlong(wq1.y);
                u64 av[8] = {A01.x, A01.y, A23.x, A23.y, A45.x, A45.y, A67.x, A67.y};
#pragma unroll
                for (int i = 0; i < 8; i++) {
                    fma2(acc2[i][0], av[i], w0);
                    fma2(acc2[i][1], av[i], w1);
                    fma2(acc2[i][2], av[i], w2);
                    fma2(acc2[i][3], av[i], w3);
                }
            }
            __syncthreads();
        }
    }

    float colS[8], colQ[8];
#pragma unroll
    for (int j = 0; j < 8; j++) { colS[j] = 0.f; colQ[j] = 0.f; }
#pragma unroll
    for (int i = 0; i < 8; i++) {
        float* Cp = Out + (size_t)(brow + ty * 8 + i) * CH + tx * 8;
        float2 p0 = upk(acc2[i][0]), p1 = upk(acc2[i][1]);
        float2 p2 = upk(acc2[i][2]), p3 = upk(acc2[i][3]);
        float c[8] = {p0.x, p0.y, p1.x, p1.y, p2.x, p2.y, p3.x, p3.y};
#pragma unroll
        for (int j = 0; j < 8; j++) { colS[j] += c[j]; colQ[j] += c[j] * c[j]; }
        *(float4*)Cp       = make_float4(c[0], c[1], c[2], c[3]);
        *(float4*)(Cp + 4) = make_float4(c[4], c[5], c[6], c[7]);
    }
    __syncthreads();
    float* red0 = &Asd[0][0];
    float* red1 = &Asd[0][128];
    if (tid < 128) { red0[tid] = 0.f; red1[tid] = 0.f; }
    __syncthreads();
#pragma unroll
    for (int j = 0; j < 8; j++) {
        atomicAdd(&red0[tx * 8 + j], colS[j]);
        atomicAdd(&red1[tx * 8 + j], colQ[j]);
    }
    __syncthreads();
    if (tid < 128) {
        atomicAdd(&sumP[tid],  red0[tid]);
        atomicAdd(&sumqP[tid], red1[tid]);
    }
}

// ---------------- BN finalize (reads + self-zeroes accumulators) -------------
__global__ void bn_finalize(float* __restrict__ sum, float* __restrict__ sumsq,
                            const float* __restrict__ gamma, const float* __restrict__ beta,
                            float* __restrict__ scale, float* __restrict__ bias)
{
    int c = threadIdx.x;
    float s = sum[c], q = sumsq[c];
    sum[c] = 0.f; sumsq[c] = 0.f;
    float m = s * (1.f / (float)NV);
    float v = q * (1.f / (float)NV) - m * m;
    float sc = gamma[c] * rsqrtf(v + 1e-5f);
    scale[c] = sc;
    bias[c] = beta[c] - m * sc;
}

// ---------------- cluster index build ----------------------------------------
__global__ void hist_k(const int* __restrict__ cl, int* __restrict__ cnt)
{
    int i = blockIdx.x * blockDim.x + threadIdx.x;
    atomicAdd(&cnt[cl[i]], 1);
}

__global__ void scan_k(int* __restrict__ cnt, int* __restrict__ off)
{
    __shared__ int s[2][NSEGS];
    int t = threadIdx.x;
    int v = cnt[t];
    cnt[t] = 0;                       // zero for next use
    s[0][t] = v;
    __syncthreads();
    int cur = 0;
    for (int d = 1; d < NSEGS; d <<= 1) {
        int nv = s[cur][t] + (t >= d ? s[cur][t - d] : 0);
        s[cur ^ 1][t] = nv;
        cur ^= 1;
        __syncthreads();
    }
    off[t + 1] = s[cur][t];
    if (t == 0) off[0] = 0;
}

__global__ void scatter_k(const int* __restrict__ cl, const int* __restrict__ off,
                          int* __restrict__ tail, int* __restrict__ order)
{
    int i = blockIdx.x * blockDim.x + threadIdx.x;
    int c = cl[i];
    int pos = atomicAdd(&tail[c], 1);
    order[off[c] + pos] = i;
}

// ---------------- segment gathers --------------------------------------------
// mean of lrelu(bn(pw)) per segment
__global__ void segmean_g(const float* __restrict__ X, const float* __restrict__ sc,
                          const float* __restrict__ sb, const int* __restrict__ off,
                          const int* __restrict__ order, float* __restrict__ Sm)
{
    int s = blockIdx.x, c = threadIdx.x;
    int b = off[s], e = off[s + 1];
    float scc = sc[c], sbc = sb[c];
    float acc = 0.f;
    for (int r = b; r < e; r++) {
        int n = order[r];
        acc += lrelu(X[(size_t)n * CH + c] * scc + sbc);
    }
    Sm[(size_t)s * CH + c] = acc / fmaxf((float)(e - b), 1.f);
}

// pw <- lrelu(bn(pw)) - segmean[cl]
__global__ void center_k(float* __restrict__ X, const float* __restrict__ sc,
                         const float* __restrict__ sb, const int* __restrict__ cl,
                         const float* __restrict__ Sm)
{
    int i = blockIdx.x * blockDim.x + threadIdx.x;
    int n = i >> 7, c = i & 127;
    float v = lrelu(X[i] * sc[c] + sb[c]);
    X[i] = v - Sm[(size_t)cl[n] * CH + c];
}

// segexp[s,c] = sum exp(t - gmax)
__global__ void segexp_g(const float* __restrict__ T, const u32* __restrict__ gmaxP,
                         const int* __restrict__ off, const int* __restrict__ order,
                         float* __restrict__ Se)
{
    int s = blockIdx.x, c = threadIdx.x;
    int b = off[s], e = off[s + 1];
    float gm = dec_max(*gmaxP);
    float acc = 0.f;
    for (int r = b; r < e; r++) {
        int n = order[r];
        acc += expf(T[(size_t)n * CH + c] - gm);
    }
    Se[(size_t)s * CH + c] = acc;
}

// seg2[s,c] = sum lrelu(bn(pf)) * exp(t-gmax) / (segexp+eps)
__global__ void seg2_g(const float* __restrict__ PF, const float* __restrict__ T,
                       const float* __restrict__ sc, const float* __restrict__ sb,
                       const u32* __restrict__ gmaxP, const float* __restrict__ Se,
                       const int* __restrict__ off, const int* __restrict__ order,
                       float* __restrict__ S2)
{
    int s = blockIdx.x, c = threadIdx.x;
    int b = off[s], e = off[s + 1];
    float gm = dec_max(*gmaxP);
    float inv = 1.f / (Se[(size_t)s * CH + c] + 1e-6f);
    float scc = sc[c], sbc = sb[c];
    float acc = 0.f;
    for (int r = b; r < e; r++) {
        int n = order[r];
        float pfv = lrelu(PF[(size_t)n * CH + c] * scc + sbc);
        acc += pfv * expf(T[(size_t)n * CH + c] - gm) * inv;
    }
    S2[(size_t)s * CH + c] = acc;
}

// agg[n,c] = sum_lvl adp[n,lvl] * seg2[lvl][cl[lvl][n], c]
__global__ void agg_k(const float* __restrict__ adp, const int* __restrict__ clusters,
                      const float* __restrict__ S2, float* __restrict__ AGG)
{
    int i = blockIdx.x * blockDim.x + threadIdx.x;
    int n = i >> 7, c = i & 127;
    float r = 0.f;
#pragma unroll
    for (int lvl = 0; lvl < 3; lvl++) {
        int s = clusters[(size_t)lvl * NV + n];
        r += adp[n * 3 + lvl] * S2[(size_t)lvl * NSEGS * CH + (size_t)s * CH + c];
    }
    AGG[i] = r;
}

// fused = lrelu(bn(t)) + feat
__global__ void fusedres_k(const float* __restrict__ T, const float* __restrict__ sc,
                           const float* __restrict__ sb, const float* __restrict__ feat,
                           float* __restrict__ F)
{
    int i = blockIdx.x * blockDim.x + threadIdx.x;
    int c = i & 127;
    F[i] = lrelu(T[i] * sc[c] + sb[c]) + feat[i];
}

// out = lrelu(bn(dbuf) + fused)
__global__ void final_k(const float* __restrict__ D, const float* __restrict__ sc,
                        const float* __restrict__ sb, const float* __restrict__ F,
                        float* __restrict__ O)
{
    int i = blockIdx.x * blockDim.x + threadIdx.x;
    int c = i & 127;
    O[i] = lrelu(D[i] * sc[c] + sb[c] + F[i]);
}

// ---------------- adaptive softmax -------------------------------------------
__global__ void adp_kernel(const float* __restrict__ feat, const float* __restrict__ aw,
                           float* __restrict__ adp)
{
    int row = blockIdx.x * 8 + (threadIdx.x >> 5);
    int lane = threadIdx.x & 31;
    float d0 = 0.f, d1 = 0.f, d2 = 0.f;
    const float* f = feat + (size_t)row * CH;
#pragma unroll
    for (int j = lane; j < CH; j += 32) {
        float v = f[j];
        d0 += v * aw[j * 3 + 0];
        d1 += v * aw[j * 3 + 1];
        d2 += v * aw[j * 3 + 2];
    }
#pragma unroll
    for (int o = 16; o; o >>= 1) {
        d0 += __shfl_xor_sync(0xffffffffu, d0, o);
        d1 += __shfl_xor_sync(0xffffffffu, d1, o);
        d2 += __shfl_xor_sync(0xffffffffu, d2, o);
    }
    if (lane == 0) {
        float m = fmaxf(d0, fmaxf(d1, d2));
        float e0 = expf(d0 - m), e1 = expf(d1 - m), e2 = expf(d2 - m);
        float inv = 1.f / (e0 + e1 + e2);
        adp[row * 3 + 0] = e0 * inv;
        adp[row * 3 + 1] = e1 * inv;
        adp[row * 3 + 2] = e2 * inv;
    }
}

// ---------------- orchestration ----------------------------------------------
extern "C" void kernel_launch(void* const* d_in, const int* in_sizes, int n_in,
                              void* d_out, int out_size)
{
    const float* feat       = (const float*)d_in[0];
    const int*   clusters   = (const int*)d_in[1];
    const int*   nbr        = (const int*)d_in[2];
    const float* lw_w       = (const float*)d_in[3];
    const float* lw_gamma   = (const float*)d_in[4];
    const float* lw_beta    = (const float*)d_in[5];
    const float* w_w        = (const float*)d_in[6];
    const float* proj_w     = (const float*)d_in[7];
    const float* proj_gamma = (const float*)d_in[8];
    const float* proj_beta  = (const float*)d_in[9];
    const float* adaptive_w = (const float*)d_in[10];
    const float* fuse_w     = (const float*)d_in[11];
    const float* fuse_gamma = (const float*)d_in[12];
    const float* fuse_beta  = (const float*)d_in[13];
    const float* conv1_w    = (const float*)d_in[14];
    const float* conv2_w    = (const float*)d_in[15];
    const float* bn1_gamma  = (const float*)d_in[16];
    const float* bn1_beta   = (const float*)d_in[17];
    const float* bn2_gamma  = (const float*)d_in[18];
    const float* bn2_beta   = (const float*)d_in[19];
    float* out = (float*)d_out;

    float *pw, *t, *pf, *agg, *fused, *ybuf, *dbuf, *adp;
    float *segmean, *segexp, *seg2, *sum, *sumsq, *scale, *bias;
    int *cnt, *tail, *off, *order;
    u32 *gmaxu;
    cudaGetSymbolAddress((void**)&pw, g_pw);
    cudaGetSymbolAddress((void**)&t, g_t);
    cudaGetSymbolAddress((void**)&pf, g_pf);
    cudaGetSymbolAddress((void**)&agg, g_agg);
    cudaGetSymbolAddress((void**)&fused, g_fused);
    cudaGetSymbolAddress((void**)&ybuf, g_ybuf);
    cudaGetSymbolAddress((void**)&dbuf, g_dbuf);
    cudaGetSymbolAddress((void**)&adp, g_adp);
    cudaGetSymbolAddress((void**)&segmean, g_segmean);
    cudaGetSymbolAddress((void**)&segexp, g_segexp);
    cudaGetSymbolAddress((void**)&seg2, g_seg2);
    cudaGetSymbolAddress((void**)&sum, g_sum);
    cudaGetSymbolAddress((void**)&sumsq, g_sumsq);
    cudaGetSymbolAddress((void**)&scale, g_scale);
    cudaGetSymbolAddress((void**)&bias, g_bias);
    cudaGetSymbolAddress((void**)&cnt, g_cnt);
    cudaGetSymbolAddress((void**)&tail, g_tail);
    cudaGetSymbolAddress((void**)&off, g_off);
    cudaGetSymbolAddress((void**)&order, g_order);
    cudaGetSymbolAddress((void**)&gmaxu, g_gmaxu);

    const int EB = 256;
    const int EG = NC / EB;

    adp_kernel<<<NV / 8, 256>>>(feat, adaptive_w, adp);

    for (int i = 0; i < 3; i++) {
        const int* cl = clusters + (size_t)i * NV;

        // index build (cnt is zero: module init on first call, scan self-zeroes after)
        hist_k<<<NV / 256, 256>>>(cl, cnt);
        scan_k<<<1, NSEGS>>>(cnt, off);
        cudaMemsetAsync(tail, 0, NSEGS * sizeof(int), 0);
        scatter_k<<<NV / 256, 256>>>(cl, off, tail, order);

        // pw = feat @ lw_w[i]  (+ colstats epilogue)
        gemm128<0, 1><<<512, 256>>>(feat, lw_w + (size_t)i * CH * CH, pw, 0,
                                    nullptr, nullptr, sum, sumsq, nullptr);
        bn_finalize<<<1, 128>>>(sum, sumsq, lw_gamma + i * CH, lw_beta + i * CH, scale, bias);

        // per-cluster mean of lrelu(bn(pw)); center pw in place
        segmean_g<<<NSEGS, 128>>>(pw, scale, bias, off, order, segmean);
        center_k<<<EG, EB>>>(pw, scale, bias, cl, segmean);

        // t = pw @ w_w[i]  (+ global max epilogue)
        cudaMemsetAsync(gmaxu, 0, sizeof(u32), 0);
        gemm128<0, 2><<<512, 256>>>(pw, w_w + (size_t)i * CH * CH, t, 0,
                                    nullptr, nullptr, nullptr, nullptr, gmaxu);

        // pf = feat @ proj_w[i]  (+ colstats epilogue)
        gemm128<0, 1><<<512, 256>>>(feat, proj_w + (size_t)i * CH * CH, pf, 0,
                                    nullptr, nullptr, sum, sumsq, nullptr);
        bn_finalize<<<1, 128>>>(sum, sumsq, proj_gamma + i * CH, proj_beta + i * CH, scale, bias);

        // per-cluster exp-sum, then weighted projection segment sum
        segexp_g<<<NSEGS, 128>>>(t, gmaxu, off, order, segexp);
        seg2_g<<<NSEGS, 128>>>(pf, t, scale, bias, gmaxu, segexp, off, order,
                               seg2 + (size_t)i * NSEGS * CH);
    }

    // agg[n,c] = sum_lvl adp * seg2
    agg_k<<<EG, EB>>>(adp, clusters, seg2, agg);

    // f_last raw = feat @ proj_w[3]
    gemm128<0, 1><<<512, 256>>>(feat, proj_w + (size_t)3 * CH * CH, pf, 0,
                                nullptr, nullptr, sum, sumsq, nullptr);
    bn_finalize<<<1, 128>>>(sum, sumsq, proj_gamma + 3 * CH, proj_beta + 3 * CH, scale, bias);

    // fuse: t = lrelu(bn(pf)) @ W0 + agg @ W1   (bn+lrelu fused into A-prologue)
    gemm128<1, 0><<<512, 256>>>(pf, fuse_w, t, 0, scale, bias, nullptr, nullptr, nullptr);
    gemm128<0, 1><<<512, 256>>>(agg, fuse_w + (size_t)CH * CH, t, 1,
                                nullptr, nullptr, sum, sumsq, nullptr);
    bn_finalize<<<1, 128>>>(sum, sumsq, fuse_gamma, fuse_beta, scale, bias);
    fusedres_k<<<EG, EB>>>(t, scale, bias, feat, fused);

    // conv1 (+ colstats)
    sconv128<0><<<512, 256>>>(fused, nbr, conv1_w, ybuf, nullptr, nullptr, sum, sumsq);
    bn_finalize<<<1, 128>>>(sum, sumsq, bn1_gamma, bn1_beta, scale, bias);

    // conv2 with bn1+lrelu fused into the gather prologue (+ colstats)
    sconv128<1><<<512, 256>>>(ybuf, nbr, conv2_w, dbuf, scale, bias, sum, sumsq);
    bn_finalize<<<1, 128>>>(sum, sumsq, bn2_gamma, bn2_beta, scale, bias);

    // out = lrelu(bn2(conv2) + fused)
    final_k<<<EG, EB>>>(dbuf, scale, bias, fused, out);
}

// round 5
// speedup vs baseline: 1.4461x; 1.4461x over previous
#include <cuda_runtime.h>
#include <cuda_bf16.h>
#include <math.h>

#define NV   65536
#define CH   128
#define NSEGS 1024
#define KT   27
#define NC   (NV*CH)

typedef unsigned long long u64;
typedef unsigned int u32;

__device__ __forceinline__ u64 pk2(float x) {
    u64 r; asm("mov.b64 %0, {%1, %1};" : "=l"(r) : "f"(x)); return r;
}
__device__ __forceinline__ void fma2(u64 &d, u64 a, u64 b) {
    asm("fma.rn.f32x2 %0, %1, %2, %0;" : "+l"(d) : "l"(a), "l"(b));
}
__device__ __forceinline__ float2 upk(u64 v) {
    float2 f; asm("mov.b64 {%0, %1}, %2;" : "=f"(f.x), "=f"(f.y) : "l"(v)); return f;
}
__device__ __forceinline__ float lrelu(float v) { return v >= 0.f ? v : 0.01f * v; }

// ---------------- scratch ----------------------------------------------------
__device__ float g_pw[NC];
__device__ float g_t[NC];
__device__ float g_pf[NC];
__device__ float g_agg[NC];
__device__ float g_fused[NC];
__device__ float g_ybuf[NC];
__device__ float g_dbuf[NC];
__device__ float g_adp[NV*3];
__device__ float g_seg[NSEGS*CH];
__device__ float g_seg2[NSEGS*CH];
__device__ float g_cnt[NSEGS];
__device__ float g_sum[CH];
__device__ float g_sumsq[CH];
__device__ float g_scale[CH];
__device__ float g_bias[CH];
__device__ float g_part[1024];
__device__ float g_gmax[1];
// HMMA conv scratch (16B-aligned for cp.async)
__device__ __align__(256) __nv_bfloat16 g_wimg[2*KT*32768]; // [conv][tap][hi 16384|lo 16384] as [cout][cin]
__device__ __align__(256) __nv_bfloat16 g_xhi[NC];
__device__ __align__(256) __nv_bfloat16 g_xlo[NC];

// ======================= HMMA (mma.sync) sparse conv ==========================
#define SMEM_STRIDE 136               // bf16 elems per smem row (pad 8 -> no conflicts)
#define TILE_BYTES  (128*SMEM_STRIDE*2)   // 34816
#define SMEMSZ      (4*TILE_BYTES)        // A_hi, A_lo, W_hi, W_lo = 139264

__device__ __forceinline__ u32 smem_u32(const void* p) {
    u32 a; asm("{ .reg .u64 t; cvta.to.shared.u64 t, %1; cvt.u32.u64 %0, t; }"
               : "=r"(a) : "l"(p));
    return a;
}
__device__ __forceinline__ void cp16(u32 dst, const void* src, u32 srcsz) {
    asm volatile("cp.async.cg.shared.global [%0], [%1], 16, %2;"
                 :: "r"(dst), "l"(src), "r"(srcsz) : "memory");
}
__device__ __forceinline__ u32 lds32(u32 addr) {
    u32 v; asm volatile("ld.shared.b32 %0, [%1];" : "=r"(v) : "r"(addr)); return v;
}
__device__ __forceinline__ void mma16816(float* c, const u32* a, const u32* b) {
    asm volatile(
        "mma.sync.aligned.m16n8k16.row.col.f32.bf16.bf16.f32 "
        "{%0,%1,%2,%3}, {%4,%5,%6,%7}, {%8,%9}, {%0,%1,%2,%3};"
        : "+f"(c[0]), "+f"(c[1]), "+f"(c[2]), "+f"(c[3])
        : "r"(a[0]), "r"(a[1]), "r"(a[2]), "r"(a[3]), "r"(b[0]), "r"(b[1]));
}

// weight prep: W[k][cin][cout] fp32 -> img[k]: hi[cout][cin], lo[cout][cin] bf16
__global__ void wprep(const float* __restrict__ W1, const float* __restrict__ W2,
                      __nv_bfloat16* __restrict__ img)
{
    int b = blockIdx.x;                       // 0..53 : conv*27 + tap
    const float* W = (b < KT ? W1 : W2) + (size_t)(b % KT) * CH * CH;
    __nv_bfloat16* o = img + (size_t)b * 32768;
    for (int u = threadIdx.x; u < 16384; u += blockDim.x) {
        int cout = u >> 7, cin = u & 127;
        float v = W[cin * CH + cout];
        __nv_bfloat16 h = __float2bfloat16(v);
        o[u]         = h;
        o[16384 + u] = __float2bfloat16(v - __bfloat162float(h));
    }
}

// Out[128/blk,128] = sum_k (mask? X[idx]:0) @ W[k], bf16 hi/lo 3-pass, fp32 acc
__global__ __launch_bounds__(256, 1)
void sconv_mma(const __nv_bfloat16* __restrict__ Xhi,
               const __nv_bfloat16* __restrict__ Xlo,
               const int* __restrict__ nbr,
               const __nv_bfloat16* __restrict__ Wimg,
               float* __restrict__ Out)
{
    extern __shared__ char dsm[];
    const u32 sb = smem_u32(dsm);
    const u32 A_HI = sb, A_LO = sb + TILE_BYTES;
    const u32 W_HI = sb + 2 * TILE_BYTES, W_LO = sb + 3 * TILE_BYTES;

    const int tid = threadIdx.x;
    const int wid = tid >> 5, lane = tid & 31;
    const int g = lane >> 2, tg = lane & 3;
    const int wm = wid & 3, wn = wid >> 2;          // warp tile: rows wm*32, cols wn*64
    const int brow = blockIdx.x * 128;

    const int cr = tid >> 1, chalf = tid & 1;       // copy role: row, 128B half

    float acc[2][8][4];
#pragma unroll
    for (int mt = 0; mt < 2; mt++)
#pragma unroll
        for (int nt = 0; nt < 8; nt++)
#pragma unroll
            for (int q = 0; q < 4; q++) acc[mt][nt][q] = 0.f;

    const u32 rowoff = (u32)cr * (SMEM_STRIDE * 2) + (u32)chalf * 128;

#pragma unroll 1
    for (int k = 0; k < KT; k++) {
        int n = nbr[(size_t)(brow + cr) * KT + k];
        bool valid = n < NV;
        u32 sz = valid ? 16u : 0u;
        const char* shi = (const char*)(Xhi + (size_t)(valid ? n : 0) * CH) + chalf * 128;
        const char* slo = (const char*)(Xlo + (size_t)(valid ? n : 0) * CH) + chalf * 128;
        const char* whi = (const char*)(Wimg + (size_t)k * 32768) + cr * 256 + chalf * 128;
        const char* wlo = whi + 32768;
#pragma unroll
        for (int j = 0; j < 8; j++) {
            cp16(A_HI + rowoff + j * 16, shi + j * 16, sz);
            cp16(A_LO + rowoff + j * 16, slo + j * 16, sz);
            cp16(W_HI + rowoff + j * 16, whi + j * 16, 16u);
            cp16(W_LO + rowoff + j * 16, wlo + j * 16, 16u);
        }
        asm volatile("cp.async.commit_group;" ::: "memory");
        asm volatile("cp.async.wait_group 0;" ::: "memory");
        __syncthreads();

#pragma unroll
        for (int kc = 0; kc < 8; kc++) {
            const u32 kb = (u32)(kc * 16 + tg * 2) * 2;   // byte offset of k pair
            u32 ah[2][4], al[2][4];
#pragma unroll
            for (int mt = 0; mt < 2; mt++) {
                u32 R = (u32)(wm * 32 + mt * 16 + g) * (SMEM_STRIDE * 2);
                u32 R8 = R + 8 * (SMEM_STRIDE * 2);
                ah[mt][0] = lds32(A_HI + R  + kb);
                ah[mt][1] = lds32(A_HI + R8 + kb);
                ah[mt][2] = lds32(A_HI + R  + kb + 16);
                ah[mt][3] = lds32(A_HI + R8 + kb + 16);
                al[mt][0] = lds32(A_LO + R  + kb);
                al[mt][1] = lds32(A_LO + R8 + kb);
                al[mt][2] = lds32(A_LO + R  + kb + 16);
                al[mt][3] = lds32(A_LO + R8 + kb + 16);
            }
            u32 bh[8][2], bl[8][2];
#pragma unroll
            for (int nt = 0; nt < 8; nt++) {
                u32 Nr = (u32)(wn * 64 + nt * 8 + g) * (SMEM_STRIDE * 2);
                bh[nt][0] = lds32(W_HI + Nr + kb);
                bh[nt][1] = lds32(W_HI + Nr + kb + 16);
                bl[nt][0] = lds32(W_LO + Nr + kb);
                bl[nt][1] = lds32(W_LO + Nr + kb + 16);
            }
#pragma unroll
            for (int mt = 0; mt < 2; mt++)
#pragma unroll
                for (int nt = 0; nt < 8; nt++) {
                    mma16816(acc[mt][nt], ah[mt], bh[nt]);
                    mma16816(acc[mt][nt], al[mt], bh[nt]);
                    mma16816(acc[mt][nt], ah[mt], bl[nt]);
                }
        }
        __syncthreads();
    }

    // epilogue: write fp32 accumulators
#pragma unroll
    for (int mt = 0; mt < 2; mt++) {
        int row0 = brow + wm * 32 + mt * 16 + g;
#pragma unroll
        for (int nt = 0; nt < 8; nt++) {
            int col = wn * 64 + nt * 8 + tg * 2;
            *(float2*)(Out + (size_t)row0 * CH + col) =
                make_float2(acc[mt][nt][0], acc[mt][nt][1]);
            *(float2*)(Out + (size_t)(row0 + 8) * CH + col) =
                make_float2(acc[mt][nt][2], acc[mt][nt][3]);
        }
    }
}

// ======================= dense GEMM (FFMA2 scalar, R2-proven) ================
__global__ __launch_bounds__(256, 2) void gemm128(const float* __restrict__ A,
                                                  const float* __restrict__ W,
                                                  float* __restrict__ Cc, int acc)
{
    __shared__ float As[16][128];
    __shared__ float Ws[16][128];
    const int tid = threadIdx.x;
    const int block_row = blockIdx.x * 128;
    const int tx = tid & 15, ty = tid >> 4;
    const int ar = tid >> 1, ac = (tid & 1) * 8;
    const int wr = tid >> 4, wc = (tid & 15) * 8;
    u64 acc2[8][4];
#pragma unroll
    for (int i = 0; i < 8; i++)
#pragma unroll
        for (int j = 0; j < 4; j++) acc2[i][j] = 0ull;

    const float* Arow = A + (size_t)(block_row + ar) * CH;
#pragma unroll 1
    for (int k0 = 0; k0 < CH; k0 += 16) {
        float4 a0 = *(const float4*)(Arow + k0 + ac);
        float4 a1 = *(const float4*)(Arow + k0 + ac + 4);
        As[ac + 0][ar] = a0.x; As[ac + 1][ar] = a0.y;
        As[ac + 2][ar] = a0.z; As[ac + 3][ar] = a0.w;
        As[ac + 4][ar] = a1.x; As[ac + 5][ar] = a1.y;
        As[ac + 6][ar] = a1.z; As[ac + 7][ar] = a1.w;
        const float* Wp = W + (size_t)(k0 + wr) * CH + wc;
        *(float4*)&Ws[wr][wc]     = *(const float4*)Wp;
        *(float4*)&Ws[wr][wc + 4] = *(const float4*)(Wp + 4);
        __syncthreads();
#pragma unroll
        for (int kk = 0; kk < 16; kk++) {
            float4 a0r = *(const float4*)&As[kk][ty * 8];
            float4 a1r = *(const float4*)&As[kk][ty * 8 + 4];
            double2 wq0 = *(const double2*)&Ws[kk][tx * 8];
            double2 wq1 = *(const double2*)&Ws[kk][tx * 8 + 4];
            u64 w0 = __double_as_longlong(wq0.x);
            u64 w1 = __double_as_longlong(wq0.y);
            u64 w2 = __double_as_longlong(wq1.x);
            u64 w3 = __double_as_longlong(wq1.y);
            u64 av[8];
            av[0] = pk2(a0r.x); av[1] = pk2(a0r.y); av[2] = pk2(a0r.z); av[3] = pk2(a0r.w);
            av[4] = pk2(a1r.x); av[5] = pk2(a1r.y); av[6] = pk2(a1r.z); av[7] = pk2(a1r.w);
#pragma unroll
            for (int i = 0; i < 8; i++) {
                fma2(acc2[i][0], av[i], w0);
                fma2(acc2[i][1], av[i], w1);
                fma2(acc2[i][2], av[i], w2);
                fma2(acc2[i][3], av[i], w3);
            }
        }
        __syncthreads();
    }
#pragma unroll
    for (int i = 0; i < 8; i++) {
        float* Cp = Cc + (size_t)(block_row + ty * 8 + i) * CH + tx * 8;
        float2 p0 = upk(acc2[i][0]), p1 = upk(acc2[i][1]);
        float2 p2 = upk(acc2[i][2]), p3 = upk(acc2[i][3]);
        float4 c0 = make_float4(p0.x, p0.y, p1.x, p1.y);
        float4 c1 = make_float4(p2.x, p2.y, p3.x, p3.y);
        if (acc) {
            float4 o0 = *(const float4*)Cp, o1 = *(const float4*)(Cp + 4);
            c0.x += o0.x; c0.y += o0.y; c0.z += o0.z; c0.w += o0.w;
            c1.x += o1.x; c1.y += o1.y; c1.z += o1.z; c1.w += o1.w;
        }
        *(float4*)Cp = c0; *(float4*)(Cp + 4) = c1;
    }
}

// ---------------- BN stats / finalize / apply -------------------------------
__global__ void colstats(const float* __restrict__ X, float* __restrict__ sum,
                         float* __restrict__ sumsq)
{
    const int rstart = blockIdx.x * 128;
    const int t = threadIdx.x;
    float s = 0.f, q = 0.f;
    const float* p = X + (size_t)rstart * CH + t;
    for (int r = 0; r < 128; r++) {
        float v = p[(size_t)r * CH];
        s += v; q += v * v;
    }
    atomicAdd(&sum[t], s);
    atomicAdd(&sumsq[t], q);
}

__global__ void bn_finalize(const float* __restrict__ sum, const float* __restrict__ sumsq,
                            const float* __restrict__ gamma, const float* __restrict__ beta,
                            float* __restrict__ scale, float* __restrict__ bias)
{
    int c = threadIdx.x;
    float m = sum[c] * (1.f / (float)NV);
    float v = sumsq[c] * (1.f / (float)NV) - m * m;
    float sc = gamma[c] * rsqrtf(v + 1e-5f);
    scale[c] = sc;
    bias[c] = beta[c] - m * sc;
}

__global__ void bn_act(const float* __restrict__ X, const float* __restrict__ scale,
                       const float* __restrict__ bias, const float* __restrict__ res,
                       float* __restrict__ Y, int mode)
{
    int i = blockIdx.x * blockDim.x + threadIdx.x;
    int c = i & 127;
    float v = X[i] * scale[c] + bias[c];
    if (mode == 2) v += res[i];
    v = lrelu(v);
    if (mode == 1) v += res[i];
    Y[i] = v;
}

// lrelu(bn(X)) -> bf16 hi/lo split
__global__ void bnact_hilo(const float* __restrict__ X, const float* __restrict__ scale,
                           const float* __restrict__ bias,
                           __nv_bfloat16* __restrict__ Hi, __nv_bfloat16* __restrict__ Lo)
{
    int i = blockIdx.x * blockDim.x + threadIdx.x;
    int c = i & 127;
    float v = lrelu(X[i] * scale[c] + bias[c]);
    __nv_bfloat16 h = __float2bfloat16(v);
    Hi[i] = h;
    Lo[i] = __float2bfloat16(v - __bfloat162float(h));
}

// fused = lrelu(bn(t)) + feat ; also hi/lo split of fused
__global__ void fusedres_hilo(const float* __restrict__ T, const float* __restrict__ sc,
                              const float* __restrict__ sb, const float* __restrict__ feat,
                              float* __restrict__ F,
                              __nv_bfloat16* __restrict__ Hi, __nv_bfloat16* __restrict__ Lo)
{
    int i = blockIdx.x * blockDim.x + threadIdx.x;
    int c = i & 127;
    float v = lrelu(T[i] * sc[c] + sb[c]) + feat[i];
    F[i] = v;
    __nv_bfloat16 h = __float2bfloat16(v);
    Hi[i] = h;
    Lo[i] = __float2bfloat16(v - __bfloat162float(h));
}

// out = lrelu(bn(dbuf) + fused)
__global__ void final_k(const float* __restrict__ D, const float* __restrict__ sc,
                        const float* __restrict__ sb, const float* __restrict__ F,
                        float* __restrict__ O)
{
    int i = blockIdx.x * blockDim.x + threadIdx.x;
    int c = i & 127;
    O[i] = lrelu(D[i] * sc[c] + sb[c] + F[i]);
}

// ---------------- segment ops (R2 atomics) -----------------------------------
__global__ void seg_count(const int* __restrict__ cl, float* __restrict__ cnt)
{
    int i = blockIdx.x * blockDim.x + threadIdx.x;
    atomicAdd(&cnt[cl[i]], 1.f);
}

__global__ void seg_sum(const float* __restrict__ X, const int* __restrict__ cl,
                        float* __restrict__ S)
{
    int i = blockIdx.x * blockDim.x + threadIdx.x;
    int n = i >> 7, c = i & 127;
    atomicAdd(&S[(size_t)cl[n] * CH + c], X[i]);
}

__global__ void sub_segmean(float* __restrict__ X, const float* __restrict__ S,
                            const float* __restrict__ cnt, const int* __restrict__ cl)
{
    int i = blockIdx.x * blockDim.x + threadIdx.x;
    int n = i >> 7, c = i & 127;
    int s = cl[n];
    X[i] -= S[(size_t)s * CH + c] / fmaxf(cnt[s], 1.f);
}

__global__ void exp_seg(float* __restrict__ T, const float* __restrict__ gmax,
                        const int* __restrict__ cl, float* __restrict__ S)
{
    int i = blockIdx.x * blockDim.x + threadIdx.x;
    int n = i >> 7, c = i & 127;
    float e = expf(T[i] - gmax[0]);
    T[i] = e;
    atomicAdd(&S[(size_t)cl[n] * CH + c], e);
}

__global__ void wmul_seg(float* __restrict__ PF, const float* __restrict__ T,
                         const float* __restrict__ S, const int* __restrict__ cl,
                         float* __restrict__ S2)
{
    int i = blockIdx.x * blockDim.x + threadIdx.x;
    int n = i >> 7, c = i & 127;
    int s = cl[n];
    float v = PF[i] * (T[i] / (S[(size_t)s * CH + c] + 1e-6f));
    PF[i] = v;
    atomicAdd(&S2[(size_t)s * CH + c], v);
}

__global__ void agg_acc(float* __restrict__ AGG, const float* __restrict__ adp, int lvl,
                        const float* __restrict__ S, const int* __restrict__ cl)
{
    int i = blockIdx.x * blockDim.x + threadIdx.x;
    int n = i >> 7, c = i & 127;
    AGG[i] += adp[n * 3 + lvl] * S[(size_t)cl[n] * CH + c];
}

// ---------------- global max (two stage) ------------------------------------
__global__ void rmax1(const float* __restrict__ X, float* __restrict__ part)
{
    __shared__ float sm[256];
    float m = -3.4e38f;
    for (int i = blockIdx.x * 256 + threadIdx.x; i < NC; i += gridDim.x * 256)
        m = fmaxf(m, X[i]);
    sm[threadIdx.x] = m;
    __syncthreads();
    for (int o = 128; o; o >>= 1) {
        if (threadIdx.x < o) sm[threadIdx.x] = fmaxf(sm[threadIdx.x], sm[threadIdx.x + o]);
        __syncthreads();
    }
    if (threadIdx.x == 0) part[blockIdx.x] = sm[0];
}

__global__ void rmax2(const float* __restrict__ part, float* __restrict__ out)
{
    __shared__ float sm[256];
    float m = -3.4e38f;
    for (int i = threadIdx.x; i < 1024; i += 256) m = fmaxf(m, part[i]);
    sm[threadIdx.x] = m;
    __syncthreads();
    for (int o = 128; o; o >>= 1) {
        if (threadIdx.x < o) sm[threadIdx.x] = fmaxf(sm[threadIdx.x], sm[threadIdx.x + o]);
        __syncthreads();
    }
    if (threadIdx.x == 0) out[0] = sm[0];
}

// ---------------- adaptive softmax -------------------------------------------
__global__ void adp_kernel(const float* __restrict__ feat, const float* __restrict__ aw,
                           float* __restrict__ adp)
{
    int row = blockIdx.x * 8 + (threadIdx.x >> 5);
    int lane = threadIdx.x & 31;
    float d0 = 0.f, d1 = 0.f, d2 = 0.f;
    const float* f = feat + (size_t)row * CH;
#pragma unroll
    for (int j = lane; j < CH; j += 32) {
        float v = f[j];
        d0 += v * aw[j * 3 + 0];
        d1 += v * aw[j * 3 + 1];
        d2 += v * aw[j * 3 + 2];
    }
#pragma unroll
    for (int o = 16; o; o >>= 1) {
        d0 += __shfl_xor_sync(0xffffffffu, d0, o);
        d1 += __shfl_xor_sync(0xffffffffu, d1, o);
        d2 += __shfl_xor_sync(0xffffffffu, d2, o);
    }
    if (lane == 0) {
        float m = fmaxf(d0, fmaxf(d1, d2));
        float e0 = expf(d0 - m), e1 = expf(d1 - m), e2 = expf(d2 - m);
        float inv = 1.f / (e0 + e1 + e2);
        adp[row * 3 + 0] = e0 * inv;
        adp[row * 3 + 1] = e1 * inv;
        adp[row * 3 + 2] = e2 * inv;
    }
}

// ---------------- orchestration ----------------------------------------------
extern "C" void kernel_launch(void* const* d_in, const int* in_sizes, int n_in,
                              void* d_out, int out_size)
{
    const float* feat       = (const float*)d_in[0];
    const int*   clusters   = (const int*)d_in[1];
    const int*   nbr        = (const int*)d_in[2];
    const float* lw_w       = (const float*)d_in[3];
    const float* lw_gamma   = (const float*)d_in[4];
    const float* lw_beta    = (const float*)d_in[5];
    const float* w_w        = (const float*)d_in[6];
    const float* proj_w     = (const float*)d_in[7];
    const float* proj_gamma = (const float*)d_in[8];
    const float* proj_beta  = (const float*)d_in[9];
    const float* adaptive_w = (const float*)d_in[10];
    const float* fuse_w     = (const float*)d_in[11];
    const float* fuse_gamma = (const float*)d_in[12];
    const float* fuse_beta  = (const float*)d_in[13];
    const float* conv1_w    = (const float*)d_in[14];
    const float* conv2_w    = (const float*)d_in[15];
    const float* bn1_gamma  = (const float*)d_in[16];
    const float* bn1_beta   = (const float*)d_in[17];
    const float* bn2_gamma  = (const float*)d_in[18];
    const float* bn2_beta   = (const float*)d_in[19];
    float* out = (float*)d_out;

    float *pw, *t, *pf, *agg, *fused, *ybuf, *dbuf, *adp, *seg, *seg2, *cnt;
    float *sum, *sumsq, *scale, *bias, *part, *gmax;
    __nv_bfloat16 *wimg, *xhi, *xlo;
    cudaGetSymbolAddress((void**)&pw, g_pw);
    cudaGetSymbolAddress((void**)&t, g_t);
    cudaGetSymbolAddress((void**)&pf, g_pf);
    cudaGetSymbolAddress((void**)&agg, g_agg);
    cudaGetSymbolAddress((void**)&fused, g_fused);
    cudaGetSymbolAddress((void**)&ybuf, g_ybuf);
    cudaGetSymbolAddress((void**)&dbuf, g_dbuf);
    cudaGetSymbolAddress((void**)&adp, g_adp);
    cudaGetSymbolAddress((void**)&seg, g_seg);
    cudaGetSymbolAddress((void**)&seg2, g_seg2);
    cudaGetSymbolAddress((void**)&cnt, g_cnt);
    cudaGetSymbolAddress((void**)&sum, g_sum);
    cudaGetSymbolAddress((void**)&sumsq, g_sumsq);
    cudaGetSymbolAddress((void**)&scale, g_scale);
    cudaGetSymbolAddress((void**)&bias, g_bias);
    cudaGetSymbolAddress((void**)&part, g_part);
    cudaGetSymbolAddress((void**)&gmax, g_gmax);
    cudaGetSymbolAddress((void**)&wimg, g_wimg);
    cudaGetSymbolAddress((void**)&xhi, g_xhi);
    cudaGetSymbolAddress((void**)&xlo, g_xlo);

    cudaFuncSetAttribute(sconv_mma, cudaFuncAttributeMaxDynamicSharedMemorySize, SMEMSZ);

    const int EB = 256;
    const int EG = NC / EB;

    auto bn_pipeline = [&](const float* X, const float* gamma, const float* beta) {
        cudaMemsetAsync(sum, 0, CH * sizeof(float), 0);
        cudaMemsetAsync(sumsq, 0, CH * sizeof(float), 0);
        colstats<<<NV / 128, 128>>>(X, sum, sumsq);
        bn_finalize<<<1, 128>>>(sum, sumsq, gamma, beta, scale, bias);
    };

    // conv weight images (independent prep)
    wprep<<<2 * KT, 256>>>(conv1_w, conv2_w, wimg);

    cudaMemsetAsync(agg, 0, (size_t)NC * sizeof(float), 0);
    adp_kernel<<<NV / 8, 256>>>(feat, adaptive_w, adp);

    for (int i = 0; i < 3; i++) {
        const int* cl = clusters + (size_t)i * NV;
        gemm128<<<512, 256>>>(feat, lw_w + (size_t)i * CH * CH, pw, 0);
        bn_pipeline(pw, lw_gamma + i * CH, lw_beta + i * CH);
        bn_act<<<EG, EB>>>(pw, scale, bias, nullptr, pw, 0);
        cudaMemsetAsync(cnt, 0, NSEGS * sizeof(float), 0);
        cudaMemsetAsync(seg, 0, (size_t)NSEGS * CH * sizeof(float), 0);
        seg_count<<<NV / 256, 256>>>(cl, cnt);
        seg_sum<<<EG, EB>>>(pw, cl, seg);
        sub_segmean<<<EG, EB>>>(pw, seg, cnt, cl);
        gemm128<<<512, 256>>>(pw, w_w + (size_t)i * CH * CH, t, 0);
        rmax1<<<1024, 256>>>(t, part);
        rmax2<<<1, 256>>>(part, gmax);
        cudaMemsetAsync(seg, 0, (size_t)NSEGS * CH * sizeof(float), 0);
        exp_seg<<<EG, EB>>>(t, gmax, cl, seg);
        gemm128<<<512, 256>>>(feat, proj_w + (size_t)i * CH * CH, pf, 0);
        bn_pipeline(pf, proj_gamma + i * CH, proj_beta + i * CH);
        bn_act<<<EG, EB>>>(pf, scale, bias, nullptr, pf, 0);
        cudaMemsetAsync(seg2, 0, (size_t)NSEGS * CH * sizeof(float), 0);
        wmul_seg<<<EG, EB>>>(pf, t, seg, cl, seg2);
        agg_acc<<<EG, EB>>>(agg, adp, i, seg2, cl);
    }

    // f_last = lrelu(bn(feat @ proj_w[3]))
    gemm128<<<512, 256>>>(feat, proj_w + (size_t)3 * CH * CH, pf, 0);
    bn_pipeline(pf, proj_gamma + 3 * CH, proj_beta + 3 * CH);
    bn_act<<<EG, EB>>>(pf, scale, bias, nullptr, pf, 0);

    // fused = lrelu(bn([f_last, agg] @ fuse_w)) + feat  (+ hi/lo split)
    gemm128<<<512, 256>>>(pf, fuse_w, t, 0);
    gemm128<<<512, 256>>>(agg, fuse_w + (size_t)CH * CH, t, 1);
    bn_pipeline(t, fuse_gamma, fuse_beta);
    fusedres_hilo<<<EG, EB>>>(t, scale, bias, feat, fused, xhi, xlo);

    // conv1 (HMMA) -> bn1 -> lrelu -> hi/lo
    sconv_mma<<<512, 256, SMEMSZ>>>(xhi, xlo, nbr, wimg, ybuf);
    bn_pipeline(ybuf, bn1_gamma, bn1_beta);
    bnact_hilo<<<EG, EB>>>(ybuf, scale, bias, xhi, xlo);

    // conv2 (HMMA) -> bn2 (+residual) -> lrelu
    sconv_mma<<<512, 256, SMEMSZ>>>(xhi, xlo, nbr, wimg + (size_t)KT * 32768, dbuf);
    bn_pipeline(dbuf, bn2_gamma, bn2_beta);
    final_k<<<EG, EB>>>(dbuf, scale, bias, fused, out);
}